// round 3
// baseline (speedup 1.0000x reference)
#include <cuda_runtime.h>
#include <math.h>

#define NB 8
#define NV 8192
#define NH 128
#define NK 128
#define NNZV 57344
#define BV (NB*NV)            // 65536
#define EROWS (1+2*NV)        // 16385
#define VCH 32                // v-chunks for spectral down
#define VCHROWS 256

// ---------------- scratch arena (liveness-aliased; no allocation) ----------------
// part   [0          .. 4,194,304)   16.8MB  specdown -> modulate
// m      [4,194,304  .. 4,325,376)    0.5MB  modulate -> specup
// hprop  [4,325,376  .. 12,713,984)  33.5MB  specup   -> mlp1     (aliased by x2)
// gradx  [12,713,984 .. 21,102,592)  33.5MB  gather   -> gradcomb (aliased by x1 lo)
// grady  [21,102,592 .. 29,491,200)  33.5MB  gather   -> gradcomb (aliased by x1 hi)
// hgrad  [29,491,200 .. 37,879,808)  33.5MB  gradcomb -> mlp1
__device__ float g_buf[37879808];
#define G_PART  (g_buf)
#define G_M     (g_buf + 4194304)
#define G_HPROP (g_buf + 4325376)
#define G_X2    (g_buf + 4325376)
#define G_GRADX (g_buf + 12713984)
#define G_GRADY (g_buf + 21102592)
#define G_X1    (g_buf + 12713984)
#define G_HGRAD (g_buf + 29491200)

__device__ float g_sum1[256], g_sq1[256], g_scale1[256], g_shift1[256];
__device__ float g_sum2[128], g_sq2[128], g_scale2[128], g_shift2[128];
__device__ int   g_cnt[BV], g_cur[BV], g_off[BV];
__device__ int   g_perm[NB*NNZV];

// ---------------- zero small state ----------------
__global__ void k_zero() {
    int i = blockIdx.x*blockDim.x + threadIdx.x;
    if (i < BV) { g_cnt[i] = 0; g_cur[i] = 0; }
    if (i < 256) { g_sum1[i] = 0.f; g_sq1[i] = 0.f; }
    if (i < 128) { g_sum2[i] = 0.f; g_sq2[i] = 0.f; }
}

// ---------------- spectral down: partial h_spec[k,h] = sum_v Ut[v,k]*h[v,h] ----------------
__global__ __launch_bounds__(256) void k_specdown(const float* __restrict__ eigs,
                                                  const float* __restrict__ h) {
    int c = blockIdx.x, b = blockIdx.y;
    int t = threadIdx.x, tx = t & 15, ty = t >> 4;
    __shared__ float As[8][128], Bs[8][128];
    float acc[8][8];
#pragma unroll
    for (int i = 0; i < 8; i++)
#pragma unroll
        for (int j = 0; j < 8; j++) acc[i][j] = 0.f;

    const float* Ut = eigs + (size_t)b*EROWS*NK + (size_t)(1+NV)*NK;
    const float* hb = h   + (size_t)b*NV*NH;
    int v0 = c*VCHROWS;
    int lr = t >> 5, lc4 = (t & 31) * 4;

    for (int vv = 0; vv < VCHROWS; vv += 8) {
        float4 a  = *(const float4*)(Ut + (size_t)(v0+vv+lr)*NK + lc4);
        float4 bb = *(const float4*)(hb + (size_t)(v0+vv+lr)*NH + lc4);
        *(float4*)&As[lr][lc4] = a;
        *(float4*)&Bs[lr][lc4] = bb;
        __syncthreads();
#pragma unroll
        for (int kk = 0; kk < 8; kk++) {
            float av[8], bv[8];
            *(float4*)&av[0] = *(const float4*)&As[kk][ty*8];
            *(float4*)&av[4] = *(const float4*)&As[kk][ty*8+4];
            *(float4*)&bv[0] = *(const float4*)&Bs[kk][tx*8];
            *(float4*)&bv[4] = *(const float4*)&Bs[kk][tx*8+4];
#pragma unroll
            for (int i = 0; i < 8; i++)
#pragma unroll
                for (int j = 0; j < 8; j++) acc[i][j] = fmaf(av[i], bv[j], acc[i][j]);
        }
        __syncthreads();
    }
    float* dst = G_PART + (size_t)(b*VCH + c)*NK*NH;
#pragma unroll
    for (int i = 0; i < 8; i++)
#pragma unroll
        for (int j = 0; j < 8; j++)
            dst[(size_t)(ty*8+i)*NH + tx*8+j] = acc[i][j];
}

// ---------------- reduce partials + band/prop modulation ----------------
__global__ void k_modulate(const float* __restrict__ eigs,
                           const float* __restrict__ ptime,
                           const float* __restrict__ bem_,
                           const float* __restrict__ bes_) {
    int k = blockIdx.x, b = blockIdx.y, hh = threadIdx.x;
    float s = 0.f;
#pragma unroll 8
    for (int c = 0; c < VCH; c++)
        s += G_PART[((size_t)(b*VCH + c)*NK + k)*NH + hh];
    float ev   = eigs[(size_t)b*EROWS*NK + k];
    float time = fmaxf(ptime[hh], 1e-6f);
    float bem  = fminf(fmaxf(bem_[hh], 1e-6f), 0.3f);
    float bes  = fmaxf(bes_[hh], 0.05f);
    float d    = bem - ev;
    float band = expf(-d*d / (2.f*bes*bes));
    float prop = expf(-ev*time);
    G_M[((size_t)b*NK + k)*NH + hh] = band * prop * s;
}

// ---------------- spectral up: h_prop[v,h] = sum_k U[v,k]*m[k,h] ----------------
__global__ __launch_bounds__(256) void k_specup(const float* __restrict__ eigs) {
    int rb = blockIdx.x, b = blockIdx.y;
    int t = threadIdx.x, tx = t & 15, ty = t >> 4;
    __shared__ float As[8][128], Bs[8][128];
    float acc[8][8];
#pragma unroll
    for (int i = 0; i < 8; i++)
#pragma unroll
        for (int j = 0; j < 8; j++) acc[i][j] = 0.f;

    const float* U  = eigs + (size_t)b*EROWS*NK + NK;   // row 1 = U[0]
    const float* mb = G_M  + (size_t)b*NK*NH;
    int v0 = rb*128;
    int vr = t >> 1, kk4a = (t & 1) * 4;
    int lr = t >> 5, lc4 = (t & 31) * 4;

    for (int k0 = 0; k0 < NK; k0 += 8) {
        float4 a = *(const float4*)(U + (size_t)(v0+vr)*NK + k0 + kk4a);
        As[kk4a+0][vr] = a.x; As[kk4a+1][vr] = a.y;
        As[kk4a+2][vr] = a.z; As[kk4a+3][vr] = a.w;
        *(float4*)&Bs[lr][lc4] = *(const float4*)(mb + (size_t)(k0+lr)*NH + lc4);
        __syncthreads();
#pragma unroll
        for (int kk = 0; kk < 8; kk++) {
            float av[8], bv[8];
            *(float4*)&av[0] = *(const float4*)&As[kk][ty*8];
            *(float4*)&av[4] = *(const float4*)&As[kk][ty*8+4];
            *(float4*)&bv[0] = *(const float4*)&Bs[kk][tx*8];
            *(float4*)&bv[4] = *(const float4*)&Bs[kk][tx*8+4];
#pragma unroll
            for (int i = 0; i < 8; i++)
#pragma unroll
                for (int j = 0; j < 8; j++) acc[i][j] = fmaf(av[i], bv[j], acc[i][j]);
        }
        __syncthreads();
    }
    float* dst = G_HPROP + (size_t)(b*NV + v0)*NH;
#pragma unroll
    for (int i = 0; i < 8; i++)
#pragma unroll
        for (int j = 0; j < 8; j++)
            dst[(size_t)(ty*8+i)*NH + tx*8+j] = acc[i][j];
}

// ---------------- CSR build for segment sum ----------------
__global__ void k_count(const int* __restrict__ gidx) {
    int i = blockIdx.x*blockDim.x + threadIdx.x;
    if (i >= NB*NNZV) return;
    int b = i / NNZV, n = i % NNZV;
    int row = gidx[(size_t)(b*2)*NNZV + n];
    atomicAdd(&g_cnt[b*NV + row], 1);
}

__global__ void k_scan() {   // 8 blocks x 1024 threads; 8 rows/thread
    int b = blockIdx.x, t = threadIdx.x;
    __shared__ int sm[1024];
    int loc[8]; int s = 0;
#pragma unroll
    for (int w = 0; w < 8; w++) { loc[w] = s; s += g_cnt[b*NV + t*8 + w]; }
    sm[t] = s; __syncthreads();
    for (int off = 1; off < 1024; off <<= 1) {
        int v = (t >= off) ? sm[t-off] : 0;
        __syncthreads();
        sm[t] += v;
        __syncthreads();
    }
    int base = (t > 0) ? sm[t-1] : 0;
#pragma unroll
    for (int w = 0; w < 8; w++) g_off[b*NV + t*8 + w] = base + loc[w];
}

__global__ void k_scatter(const int* __restrict__ gidx) {
    int i = blockIdx.x*blockDim.x + threadIdx.x;
    if (i >= NB*NNZV) return;
    int b = i / NNZV, n = i % NNZV;
    int row = gidx[(size_t)(b*2)*NNZV + n];
    int pos = g_off[b*NV + row] + atomicAdd(&g_cur[b*NV + row], 1);
    g_perm[(size_t)b*NNZV + pos] = n;
}

// one warp per output row; clip folded into store
__global__ __launch_bounds__(256) void k_gather(const float* __restrict__ h,
                                                const float* __restrict__ gvals,
                                                const int* __restrict__ gidx) {
    int warp = (blockIdx.x*blockDim.x + threadIdx.x) >> 5;
    int lane = threadIdx.x & 31;
    if (warp >= BV) return;
    int b = warp / NV, v = warp % NV;
    int start = g_off[b*NV + v];
    int end   = (v == NV-1) ? NNZV : g_off[b*NV + v + 1];
    float4 ax = {0.f,0.f,0.f,0.f}, ay = {0.f,0.f,0.f,0.f};
    const float* hb   = h + (size_t)b*NV*NH;
    const int*   colp = gidx  + (size_t)(b*2+1)*NNZV;
    const float* vx   = gvals + (size_t)(b*2)*NNZV;
    const float* vy   = vx + NNZV;
    const int*   perm = g_perm + (size_t)b*NNZV;
    for (int e = start; e < end; e++) {
        int n = perm[e];
        int col = colp[n];
        float sx = vx[n], sy = vy[n];
        float4 hv = *(const float4*)(hb + (size_t)col*NH + lane*4);
        ax.x = fmaf(sx, hv.x, ax.x); ax.y = fmaf(sx, hv.y, ax.y);
        ax.z = fmaf(sx, hv.z, ax.z); ax.w = fmaf(sx, hv.w, ax.w);
        ay.x = fmaf(sy, hv.x, ay.x); ay.y = fmaf(sy, hv.y, ay.y);
        ay.z = fmaf(sy, hv.z, ay.z); ay.w = fmaf(sy, hv.w, ay.w);
    }
    ax.x = fminf(fmaxf(ax.x,-1.f),1.f); ax.y = fminf(fmaxf(ax.y,-1.f),1.f);
    ax.z = fminf(fmaxf(ax.z,-1.f),1.f); ax.w = fminf(fmaxf(ax.w,-1.f),1.f);
    ay.x = fminf(fmaxf(ay.x,-1.f),1.f); ay.y = fminf(fmaxf(ay.y,-1.f),1.f);
    ay.z = fminf(fmaxf(ay.z,-1.f),1.f); ay.w = fminf(fmaxf(ay.w,-1.f),1.f);
    size_t o = (size_t)(b*NV + v)*NH + lane*4;
    *(float4*)(G_GRADX + o) = ax;
    *(float4*)(G_GRADY + o) = ay;
}

// ---------------- 4 fused GEMMs + cross/normal reduction ----------------
// h_grad[v,h] = (gxWg * gyWg2 - gyWg * gxWg2) * c[v],  c[v] = (gbx x gby) . vn
__global__ __launch_bounds__(256) void k_gradcomb(const float* __restrict__ Wg,
                                                  const float* __restrict__ Wg2,
                                                  const float* __restrict__ gbasis,
                                                  const float* __restrict__ vnorm) {
    int cb = blockIdx.x, rb = blockIdx.y, b = blockIdx.z;
    int t = threadIdx.x, tx = t & 15, ty = t >> 4;
    int v0 = rb*64, h0 = cb*64;
    __shared__ float Asx[8][64], Asy[8][64], Bsg[8][64], Bsg2[8][64];
    __shared__ float c_s[64];

    if (t < 64) {
        const float* gb = gbasis + (size_t)(b*NV + v0 + t)*6;
        const float* vn = vnorm  + (size_t)(b*NV + v0 + t)*3;
        float bx0 = gb[0], bx1 = gb[1], bx2 = gb[2];
        float by0 = gb[3], by1 = gb[4], by2 = gb[5];
        float cx = bx1*by2 - bx2*by1;
        float cy = bx2*by0 - bx0*by2;
        float cz = bx0*by1 - bx1*by0;
        c_s[t] = cx*vn[0] + cy*vn[1] + cz*vn[2];
    }

    float accA[4][4], accB[4][4], accC[4][4], accD[4][4];
#pragma unroll
    for (int i = 0; i < 4; i++)
#pragma unroll
        for (int j = 0; j < 4; j++) { accA[i][j]=0.f; accB[i][j]=0.f; accC[i][j]=0.f; accD[i][j]=0.f; }

    size_t gbase = (size_t)(b*NV + v0)*NH;
    __syncthreads();

    for (int k0 = 0; k0 < NH; k0 += 8) {
#pragma unroll
        for (int it = 0; it < 2; it++) {
            int idx = t + it*256;
            int m   = idx >> 7;
            int r   = (idx & 127) >> 1;
            int kk4 = (idx & 1) * 4;
            float4 val; float* dst;
            if (m == 0)      { val = *(const float4*)(G_GRADX + gbase + (size_t)r*NH + k0 + kk4); dst = &Asx[0][0]; }
            else if (m == 1) { val = *(const float4*)(G_GRADY + gbase + (size_t)r*NH + k0 + kk4); dst = &Asy[0][0]; }
            else if (m == 2) { val = *(const float4*)(Wg  + (size_t)(h0+r)*NH + k0 + kk4); dst = &Bsg[0][0]; }
            else             { val = *(const float4*)(Wg2 + (size_t)(h0+r)*NH + k0 + kk4); dst = &Bsg2[0][0]; }
            dst[(kk4+0)*64 + r] = val.x; dst[(kk4+1)*64 + r] = val.y;
            dst[(kk4+2)*64 + r] = val.z; dst[(kk4+3)*64 + r] = val.w;
        }
        __syncthreads();
#pragma unroll
        for (int kk = 0; kk < 8; kk++) {
            float ax[4], ay[4], bg[4], bg2v[4];
            *(float4*)&ax[0]  = *(const float4*)&Asx[kk][ty*4];
            *(float4*)&ay[0]  = *(const float4*)&Asy[kk][ty*4];
            *(float4*)&bg[0]  = *(const float4*)&Bsg[kk][tx*4];
            *(float4*)&bg2v[0]= *(const float4*)&Bsg2[kk][tx*4];
#pragma unroll
            for (int i = 0; i < 4; i++)
#pragma unroll
                for (int j = 0; j < 4; j++) {
                    accA[i][j] = fmaf(ax[i], bg[j],   accA[i][j]);
                    accB[i][j] = fmaf(ay[i], bg2v[j], accB[i][j]);
                    accC[i][j] = fmaf(ay[i], bg[j],   accC[i][j]);
                    accD[i][j] = fmaf(ax[i], bg2v[j], accD[i][j]);
                }
        }
        __syncthreads();
    }
#pragma unroll
    for (int i = 0; i < 4; i++) {
        float cc = c_s[ty*4 + i];
#pragma unroll
        for (int j = 0; j < 4; j++)
            G_HGRAD[gbase + (size_t)(ty*4+i)*NH + h0 + tx*4 + j] =
                (accA[i][j]*accB[i][j] - accC[i][j]*accD[i][j]) * cc;
    }
}

// ---------------- MLP1: x1 = concat[h, hprop, hgrad] @ W1^T + b1 ----------------
__global__ __launch_bounds__(256) void k_mlp1(const float* __restrict__ h,
                                              const float* __restrict__ W1,
                                              const float* __restrict__ b1) {
    int cb = blockIdx.x, rbk = blockIdx.y;
    int t = threadIdx.x, tx = t & 15, ty = t >> 4;
    int o0 = cb*128, r0 = rbk*128;
    __shared__ float As[8][128], Bs[8][128];
    float acc[8][8];
#pragma unroll
    for (int i = 0; i < 8; i++)
#pragma unroll
        for (int j = 0; j < 8; j++) acc[i][j] = 0.f;

    int vr = t >> 1, kk4 = (t & 1) * 4;  // shared mapping for A and B loads

    for (int f0 = 0; f0 < 384; f0 += 8) {
        const float* src = (f0 < 128) ? h : (f0 < 256) ? G_HPROP : G_HGRAD;
        int off = f0 & 127;
        float4 a = *(const float4*)(src + (size_t)(r0+vr)*NH + off + kk4);
        As[kk4+0][vr] = a.x; As[kk4+1][vr] = a.y; As[kk4+2][vr] = a.z; As[kk4+3][vr] = a.w;
        float4 w = *(const float4*)(W1 + (size_t)(o0+vr)*384 + f0 + kk4);
        Bs[kk4+0][vr] = w.x; Bs[kk4+1][vr] = w.y; Bs[kk4+2][vr] = w.z; Bs[kk4+3][vr] = w.w;
        __syncthreads();
#pragma unroll
        for (int kk = 0; kk < 8; kk++) {
            float av[8], bv[8];
            *(float4*)&av[0] = *(const float4*)&As[kk][ty*8];
            *(float4*)&av[4] = *(const float4*)&As[kk][ty*8+4];
            *(float4*)&bv[0] = *(const float4*)&Bs[kk][tx*8];
            *(float4*)&bv[4] = *(const float4*)&Bs[kk][tx*8+4];
#pragma unroll
            for (int i = 0; i < 8; i++)
#pragma unroll
                for (int j = 0; j < 8; j++) acc[i][j] = fmaf(av[i], bv[j], acc[i][j]);
        }
        __syncthreads();
    }
#pragma unroll
    for (int i = 0; i < 8; i++)
#pragma unroll
        for (int j = 0; j < 8; j++)
            G_X1[(size_t)(r0 + ty*8+i)*256 + o0 + tx*8 + j] = acc[i][j] + b1[o0 + tx*8 + j];
}

// ---------------- BN stats ----------------
__global__ void k_stats1() {
    int t = threadIdx.x;          // 256 cols
    int r0 = blockIdx.x * 512;
    float s = 0.f, s2 = 0.f;
    for (int r = r0; r < r0 + 512; r++) {
        float v = G_X1[(size_t)r*256 + t];
        s += v; s2 += v*v;
    }
    atomicAdd(&g_sum1[t], s);
    atomicAdd(&g_sq1[t], s2);
}
__global__ void k_fin1(const float* __restrict__ gamma, const float* __restrict__ beta) {
    int t = threadIdx.x;
    if (t < 256) {
        float mean = g_sum1[t] / (float)BV;
        float var  = g_sq1[t] / (float)BV - mean*mean;
        float inv  = rsqrtf(var + 1e-5f);
        float sc   = gamma[t]*inv;
        g_scale1[t] = sc;
        g_shift1[t] = beta[t] - mean*sc;
    }
}
__global__ void k_stats2() {
    int t = threadIdx.x;          // 128 cols
    int r0 = blockIdx.x * 512;
    float s = 0.f, s2 = 0.f;
    for (int r = r0; r < r0 + 512; r++) {
        float v = G_X2[(size_t)r*128 + t];
        s += v; s2 += v*v;
    }
    atomicAdd(&g_sum2[t], s);
    atomicAdd(&g_sq2[t], s2);
}
__global__ void k_fin2(const float* __restrict__ gamma, const float* __restrict__ beta) {
    int t = threadIdx.x;
    if (t < 128) {
        float mean = g_sum2[t] / (float)BV;
        float var  = g_sq2[t] / (float)BV - mean*mean;
        float inv  = rsqrtf(var + 1e-5f);
        float sc   = gamma[t]*inv;
        g_scale2[t] = sc;
        g_shift2[t] = beta[t] - mean*sc;
    }
}

// ---------------- MLP2: x2 = relu(bn1(x1)) @ W2^T + b2 (bn fused in A-load) ----------------
__global__ __launch_bounds__(256) void k_mlp2(const float* __restrict__ W2,
                                              const float* __restrict__ b2) {
    int rbk = blockIdx.x;
    int t = threadIdx.x, tx = t & 15, ty = t >> 4;
    int r0 = rbk*128;
    __shared__ float As[8][128], Bs[8][128];
    __shared__ float s1[256], sh1[256];
    s1[t] = g_scale1[t]; sh1[t] = g_shift1[t];
    __syncthreads();

    float acc[8][8];
#pragma unroll
    for (int i = 0; i < 8; i++)
#pragma unroll
        for (int j = 0; j < 8; j++) acc[i][j] = 0.f;

    int vr = t >> 1, kk4 = (t & 1) * 4;

    for (int f0 = 0; f0 < 256; f0 += 8) {
        float4 a = *(const float4*)(G_X1 + (size_t)(r0+vr)*256 + f0 + kk4);
        a.x = fmaxf(a.x*s1[f0+kk4+0] + sh1[f0+kk4+0], 0.f);
        a.y = fmaxf(a.y*s1[f0+kk4+1] + sh1[f0+kk4+1], 0.f);
        a.z = fmaxf(a.z*s1[f0+kk4+2] + sh1[f0+kk4+2], 0.f);
        a.w = fmaxf(a.w*s1[f0+kk4+3] + sh1[f0+kk4+3], 0.f);
        As[kk4+0][vr] = a.x; As[kk4+1][vr] = a.y; As[kk4+2][vr] = a.z; As[kk4+3][vr] = a.w;
        float4 w = *(const float4*)(W2 + (size_t)vr*256 + f0 + kk4);
        Bs[kk4+0][vr] = w.x; Bs[kk4+1][vr] = w.y; Bs[kk4+2][vr] = w.z; Bs[kk4+3][vr] = w.w;
        __syncthreads();
#pragma unroll
        for (int kk = 0; kk < 8; kk++) {
            float av[8], bv[8];
            *(float4*)&av[0] = *(const float4*)&As[kk][ty*8];
            *(float4*)&av[4] = *(const float4*)&As[kk][ty*8+4];
            *(float4*)&bv[0] = *(const float4*)&Bs[kk][tx*8];
            *(float4*)&bv[4] = *(const float4*)&Bs[kk][tx*8+4];
#pragma unroll
            for (int i = 0; i < 8; i++)
#pragma unroll
                for (int j = 0; j < 8; j++) acc[i][j] = fmaf(av[i], bv[j], acc[i][j]);
        }
        __syncthreads();
    }
#pragma unroll
    for (int i = 0; i < 8; i++)
#pragma unroll
        for (int j = 0; j < 8; j++)
            G_X2[(size_t)(r0 + ty*8+i)*128 + tx*8 + j] = acc[i][j] + b2[tx*8 + j];
}

// ---------------- final: out = h + bn2(x2) ----------------
__global__ void k_final(const float* __restrict__ h, float* __restrict__ out) {
    size_t i = (size_t)blockIdx.x*blockDim.x + threadIdx.x;
    if (i < (size_t)BV*NH) {
        int c = (int)(i & 127);
        out[i] = h[i] + g_scale2[c]*G_X2[i] + g_shift2[c];
    }
}

// ---------------- launch ----------------
extern "C" void kernel_launch(void* const* d_in, const int* in_sizes, int n_in,
                              void* d_out, int out_size) {
    const float* h      = (const float*)d_in[0];
    const float* eigs   = (const float*)d_in[1];
    const float* gvals  = (const float*)d_in[2];
    const int*   gidx   = (const int*)  d_in[3];
    const float* gbasis = (const float*)d_in[4];
    const float* vnorm  = (const float*)d_in[5];
    const float* ptime  = (const float*)d_in[6];
    const float* bem    = (const float*)d_in[7];
    const float* bes    = (const float*)d_in[8];
    const float* Wg     = (const float*)d_in[9];
    const float* Wg2    = (const float*)d_in[10];
    const float* W1     = (const float*)d_in[11];
    const float* b1     = (const float*)d_in[12];
    const float* gamma1 = (const float*)d_in[13];
    const float* beta1  = (const float*)d_in[14];
    const float* W2     = (const float*)d_in[15];
    const float* b2     = (const float*)d_in[16];
    const float* gamma2 = (const float*)d_in[17];
    const float* beta2  = (const float*)d_in[18];
    float* out = (float*)d_out;

    k_zero<<<256, 256>>>();
    k_specdown<<<dim3(VCH, NB), 256>>>(eigs, h);
    k_modulate<<<dim3(NK, NB), NH>>>(eigs, ptime, bem, bes);
    k_specup<<<dim3(NV/128, NB), 256>>>(eigs);
    k_count<<<(NB*NNZV + 255)/256, 256>>>(gidx);
    k_scan<<<NB, 1024>>>();
    k_scatter<<<(NB*NNZV + 255)/256, 256>>>(gidx);
    k_gather<<<BV/8, 256>>>(h, gvals, gidx);
    k_gradcomb<<<dim3(2, NV/64, NB), 256>>>(Wg, Wg2, gbasis, vnorm);
    k_mlp1<<<dim3(2, BV/128), 256>>>(h, W1, b1);
    k_stats1<<<128, 256>>>();
    k_fin1<<<1, 256>>>(gamma1, beta1);
    k_mlp2<<<BV/128, 256>>>(W2, b2);
    k_stats2<<<128, 128>>>();
    k_fin2<<<1, 128>>>(gamma2, beta2);
    k_final<<<(int)(((size_t)BV*NH + 255)/256), 256>>>(h, out);
}